// round 11
// baseline (speedup 1.0000x reference)
#include <cuda_runtime.h>
#include <cuda_fp16.h>
#include <cstdint>

#define NEG_SLOPE 0.015f
#define HH    128
#define O_DIM 128

// Scratch: segment sums [G, HH], per-graph counts, fp16 transposed W1.
__device__ float g_hsum[1 << 21];
__device__ float g_counts[1 << 16];
__device__ __half g_W1h[128 * 256];   // [n][k], k contiguous

static __device__ __forceinline__ uint32_t smem_u32(const void* p) {
    uint32_t a;
    asm("{ .reg .u64 t; cvta.to.shared.u64 t, %1; cvt.u32.u64 %0, t; }" : "=r"(a) : "l"(p));
    return a;
}
static __device__ __forceinline__ void ldsm4(uint32_t* r, uint32_t addr) {
    asm volatile("ldmatrix.sync.aligned.m8n8.x4.shared.b16 {%0,%1,%2,%3}, [%4];"
                 : "=r"(r[0]), "=r"(r[1]), "=r"(r[2]), "=r"(r[3]) : "r"(addr));
}
static __device__ __forceinline__ void mma16816(float* d, const uint32_t* a,
                                                const uint32_t* b) {
    asm volatile("mma.sync.aligned.m16n8k16.row.col.f32.f16.f16.f32 "
                 "{%0,%1,%2,%3}, {%4,%5,%6,%7}, {%8,%9}, {%0,%1,%2,%3};"
                 : "+f"(d[0]), "+f"(d[1]), "+f"(d[2]), "+f"(d[3])
                 : "r"(a[0]), "r"(a[1]), "r"(a[2]), "r"(a[3]), "r"(b[0]), "r"(b[1]));
}
static __device__ __forceinline__ void cp16(uint32_t dst, const void* src) {
    asm volatile("cp.async.cg.shared.global [%0], [%1], 16;" :: "r"(dst), "l"(src));
}
#define CP_COMMIT() asm volatile("cp.async.commit_group;" ::: "memory")
#define CP_WAIT1()  asm volatile("cp.async.wait_group 1;" ::: "memory")

// Zero scratch + W1 -> fp16, transposed to [n][k].
__global__ void prep_kernel(const float* __restrict__ W1, int hsumN, int G) {
    int i = blockIdx.x * blockDim.x + threadIdx.x;
    if (i < hsumN) g_hsum[i] = 0.f;
    if (i < G)     g_counts[i] = 0.f;
    if (i < 256 * 128) {
        int k = i >> 7, n = i & 127;          // W1 is [256][128] row-major
        g_W1h[n * 256 + k] = __float2half_rn(W1[i]);
    }
}

// SMEM (bytes):
//  [0,512)  sbid[128]
//  F16A: 2 slots x 10240 (A fp16, row stride 80B)
//  F16B: 3 slots x 10240 (B fp16, row stride 80B)
//  [1024,..) reused as Os[128][130] floats in the epilogue
#define F16A  1024
#define F16B  (F16A + 2 * 10240)
#define SMEM_BYTES (1024 + 128 * 130 * 4)   // 67584 > pipeline's 52224

extern "C" __global__ void __launch_bounds__(256, 2)
fused1(const float* __restrict__ v, const int* __restrict__ batch,
       const float* __restrict__ b1, int N)
{
    extern __shared__ __align__(128) char smem[];
    int*   sbid = (int*)smem;
    float* Os   = (float*)(smem + 1024);
    uint32_t sb = smem_u32(smem);

    int t = threadIdx.x, lid = t & 31, wid = t >> 5;
    int wm = wid & 3, wn = wid >> 2;          // warp tile: rows wm*32, cols wn*64
    long long r0 = (long long)blockIdx.x * 128;
    int valid = N - (int)r0; if (valid > 128) valid = 128;
    if (t < 128) sbid[t] = (t < valid) ? batch[r0 + t] : -1;

    // Accumulators, bias-initialized. d[mt][nt][0..3]
    float d[2][8][4];
    {
        int cb = wn * 64 + 2 * (lid & 3);
#pragma unroll
        for (int nt = 0; nt < 8; ++nt) {
            float bx = __ldg(b1 + cb + nt * 8);
            float by = __ldg(b1 + cb + nt * 8 + 1);
#pragma unroll
            for (int mt = 0; mt < 2; ++mt) {
                d[mt][nt][0] = bx; d[mt][nt][1] = by;
                d[mt][nt][2] = bx; d[mt][nt][3] = by;
            }
        }
    }

    const float* vb = v + r0 * 256;
    int r8 = lid & 7, grp = lid >> 3;

    // ONE register prefetch set (16 regs) — avoids the R10 spill.
    float4 areg[4];
    auto lda = [&](int c) {
#pragma unroll
        for (int q = 0; q < 4; ++q) {
            int idx = q * 256 + t, row = idx >> 3, f4 = idx & 7;
            int gr = (row < valid) ? row : (valid - 1);
            areg[q] = *(const float4*)(vb + (long long)gr * 256 + c * 32 + f4 * 4);
        }
    };
    auto sta = [&](int slot) {   // convert+store A (fp16) from areg
        char* base = smem + F16A + slot * 10240;
#pragma unroll
        for (int q = 0; q < 4; ++q) {
            int idx = q * 256 + t, row = idx >> 3, f4 = idx & 7;
            float4 a = areg[q];
            __half2 h01 = __floats2half2_rn(a.x, a.y);
            __half2 h23 = __floats2half2_rn(a.z, a.w);
            *(uint2*)(base + row * 80 + f4 * 8) =
                make_uint2(*(uint32_t*)&h01, *(uint32_t*)&h23);
        }
    };
    auto cpB = [&](int ch, int slot) {   // cp.async B fp16 chunk ch -> slot
        uint32_t base = sb + F16B + slot * 10240;
#pragma unroll
        for (int q = 0; q < 2; ++q) {
            int idx = q * 256 + t;
            int nn = idx >> 2, kk4 = idx & 3;
            cp16(base + nn * 80 + kk4 * 16, g_W1h + nn * 256 + ch * 32 + kk4 * 8);
        }
    };

    // ---- prologue ----
    lda(0);
    sta(0);                         // chunk0 -> f16A slot0
    lda(1);                         // prefetch chunk1 (consumed iter0's sta)
    cpB(0, 0); CP_COMMIT();         // G1 = {B0}
    cpB(1, 1); CP_COMMIT();         // G2 = {B1}
    CP_WAIT1();                     // B0 arrived
    __syncthreads();

    for (int c = 0; c < 8; ++c) {
        int s = c & 1;
        // 1) store chunk c+1 (already in regs) into the free A slot
        if (c < 7) sta(s ^ 1);
        // 2) issue LDG for chunk c+2 NOW — covered by the MMA phase below
        if (c < 6) lda(c + 2);
        // 3) B ring refill (2-chunk lead)
        if (c < 6) cpB(c + 2, (c + 2) % 3);
        CP_COMMIT();

        // 4) MMA phase on slot s (chunk c)
        uint32_t abA = sb + F16A + s * 10240;
        uint32_t abB = sb + F16B + (c % 3) * 10240;
#pragma unroll
        for (int kk = 0; kk < 2; ++kk) {
            int k0 = kk * 16;
            int arow = wm * 32 + r8 + (grp & 1) * 8;
            int acol = k0 + (grp >> 1) * 8;
            uint32_t afh[2][4];
#pragma unroll
            for (int mt = 0; mt < 2; ++mt)
                ldsm4(afh[mt], abA + (arow + mt * 16) * 80 + acol * 2);
#pragma unroll
            for (int ng = 0; ng < 4; ++ng) {
                int nrow = wn * 64 + ng * 16 + r8 + (grp >> 1) * 8;
                int ncol = k0 + (grp & 1) * 8;
                uint32_t bh[4];
                ldsm4(bh, abB + nrow * 80 + ncol * 2);
#pragma unroll
                for (int mt = 0; mt < 2; ++mt) {
#pragma unroll
                    for (int sub = 0; sub < 2; ++sub)
                        mma16816(d[mt][ng * 2 + sub], afh[mt], bh + 2 * sub);
                }
            }
        }

        CP_WAIT1();     // B_{c+1} guaranteed resident; B_{c+2} still in flight
        __syncthreads();
    }

    // Epilogue: LeakyReLU, stage tile (stride 130 floats)
#pragma unroll
    for (int mt = 0; mt < 2; ++mt) {
        int rA = wm * 32 + mt * 16 + (lid >> 2);
#pragma unroll
        for (int nt = 0; nt < 8; ++nt) {
            int cc = wn * 64 + nt * 8 + 2 * (lid & 3);
            float x0 = d[mt][nt][0], x1 = d[mt][nt][1];
            float x2 = d[mt][nt][2], x3 = d[mt][nt][3];
            x0 = (x0 >= 0.f) ? x0 : NEG_SLOPE * x0;
            x1 = (x1 >= 0.f) ? x1 : NEG_SLOPE * x1;
            x2 = (x2 >= 0.f) ? x2 : NEG_SLOPE * x2;
            x3 = (x3 >= 0.f) ? x3 : NEG_SLOPE * x3;
            *(float2*)(Os + rA * 130 + cc)       = make_float2(x0, x1);
            *(float2*)(Os + (rA + 8) * 130 + cc) = make_float2(x2, x3);
        }
    }
    __syncthreads();

    // Segmented column-sum + counts (batch sorted -> few runs per tile)
    {
        int col = t & 127, half = t >> 7;
        int rb = half * 64;
        int re = rb + 64; if (re > valid) re = valid;
        if (rb < re) {
            int cur = sbid[rb];
            float acc = 0.f; int cnt = 0;
            for (int r = rb; r < re; ++r) {
                int g = sbid[r];
                if (g != cur) {
                    atomicAdd(&g_hsum[(long long)cur * HH + col], acc);
                    if (col == 0) atomicAdd(&g_counts[cur], (float)cnt);
                    acc = 0.f; cnt = 0; cur = g;
                }
                acc += Os[r * 130 + col];
                cnt++;
            }
            atomicAdd(&g_hsum[(long long)cur * HH + col], acc);
            if (col == 0) atomicAdd(&g_counts[cur], (float)cnt);
        }
    }
}

// out[g,:] = (hsum[g,:]/max(cnt,1)) @ W2 + b2 ; empty graphs -> 0. 16 graphs/block.
__global__ void __launch_bounds__(256)
kernelB(const float* __restrict__ W2, const float* __restrict__ b2,
        float* __restrict__ out, int G)
{
    __shared__ float sh[16][130];   // col 128 = non-empty flag
    int g0 = blockIdx.x * 16;
    int t = threadIdx.x;
    for (int idx = t; idx < 16 * 128; idx += 256) {
        int r = idx >> 7, k = idx & 127;
        int g = g0 + r;
        float val = 0.f, flag = 0.f;
        if (g < G) {
            float cnt = g_counts[g];
            float dn = (cnt < 1.f) ? 1.f : cnt;
            val = g_hsum[(long long)g * HH + k] / dn;
            flag = (cnt >= 0.5f) ? 1.f : 0.f;
        }
        sh[r][k] = val;
        if (k == 0) sh[r][128] = flag;
    }
    __syncthreads();

    int col = t & 127, rg = t >> 7;
    float bv = b2[col];
    float acc[8];
#pragma unroll
    for (int r = 0; r < 8; ++r) acc[r] = bv;
#pragma unroll 4
    for (int k = 0; k < 128; ++k) {
        float w = W2[k * O_DIM + col];
#pragma unroll
        for (int r = 0; r < 8; ++r) acc[r] += sh[rg * 8 + r][k] * w;
    }
#pragma unroll
    for (int r = 0; r < 8; ++r) {
        int g = g0 + rg * 8 + r;
        if (g < G) out[(long long)g * O_DIM + col] = acc[r] * sh[rg * 8 + r][128];
    }
}

extern "C" void kernel_launch(void* const* d_in, const int* in_sizes, int n_in,
                              void* d_out, int out_size)
{
    const float* v     = (const float*)d_in[0];
    const int*   batch = (const int*)d_in[1];
    int w = 2;
    if (n_in >= 7 && in_sizes[2] == 1) w = 3;   // skip num_graphs scalar if present
    const float* W1 = (const float*)d_in[w];
    const float* b1 = (const float*)d_in[w + 1];
    const float* W2 = (const float*)d_in[w + 2];
    const float* b2 = (const float*)d_in[w + 3];

    int N = in_sizes[1];
    int G = out_size / O_DIM;
    int hsumN = G * HH;

    int zn = hsumN; if (zn < G) zn = G; if (zn < 256 * 128) zn = 256 * 128;
    prep_kernel<<<(zn + 255) / 256, 256>>>(W1, hsumN, G);

    static int smem_set = 0;
    if (!smem_set) {
        cudaFuncSetAttribute((const void*)fused1,
                             cudaFuncAttributeMaxDynamicSharedMemorySize, SMEM_BYTES);
        smem_set = 1;
    }
    int nb = (N + 127) / 128;
    fused1<<<nb, 256, SMEM_BYTES>>>(v, batch, b1, N);

    kernelB<<<(G + 15) / 16, 256>>>(W2, b2, (float*)d_out, G);
}

// round 12
// speedup vs baseline: 1.2024x; 1.2024x over previous
#include <cuda_runtime.h>
#include <cuda_fp16.h>
#include <cstdint>

#define NEG_SLOPE 0.015f
#define HH    128
#define O_DIM 128

// Scratch: segment sums [G, HH], per-graph counts, fp16 transposed W1.
__device__ float g_hsum[1 << 21];
__device__ float g_counts[1 << 16];
__device__ __half g_W1h[128 * 256];   // [n][k], k contiguous

static __device__ __forceinline__ uint32_t smem_u32(const void* p) {
    uint32_t a;
    asm("{ .reg .u64 t; cvta.to.shared.u64 t, %1; cvt.u32.u64 %0, t; }" : "=r"(a) : "l"(p));
    return a;
}
static __device__ __forceinline__ void ldsm4(uint32_t* r, uint32_t addr) {
    asm volatile("ldmatrix.sync.aligned.m8n8.x4.shared.b16 {%0,%1,%2,%3}, [%4];"
                 : "=r"(r[0]), "=r"(r[1]), "=r"(r[2]), "=r"(r[3]) : "r"(addr));
}
static __device__ __forceinline__ void mma16816(float* d, const uint32_t* a,
                                                const uint32_t* b) {
    asm volatile("mma.sync.aligned.m16n8k16.row.col.f32.f16.f16.f32 "
                 "{%0,%1,%2,%3}, {%4,%5,%6,%7}, {%8,%9}, {%0,%1,%2,%3};"
                 : "+f"(d[0]), "+f"(d[1]), "+f"(d[2]), "+f"(d[3])
                 : "r"(a[0]), "r"(a[1]), "r"(a[2]), "r"(a[3]), "r"(b[0]), "r"(b[1]));
}
static __device__ __forceinline__ void cp16(uint32_t dst, const void* src) {
    asm volatile("cp.async.cg.shared.global [%0], [%1], 16;" :: "r"(dst), "l"(src));
}
#define CP_COMMIT() asm volatile("cp.async.commit_group;" ::: "memory")
#define CP_WAIT1()  asm volatile("cp.async.wait_group 1;" ::: "memory")

// Zero scratch + W1 -> fp16, transposed to [n][k].
__global__ void prep_kernel(const float* __restrict__ W1, int hsumN, int G) {
    int i = blockIdx.x * blockDim.x + threadIdx.x;
    if (i < hsumN) g_hsum[i] = 0.f;
    if (i < G)     g_counts[i] = 0.f;
    if (i < 256 * 128) {
        int k = i >> 7, n = i & 127;          // W1 is [256][128] row-major
        g_W1h[n * 256 + k] = __float2half_rn(W1[i]);
    }
}

// SMEM (bytes):
//  [0,512)     sbid[128]
//  F32A: 3 slots x 16384  (A fp32 staging, row stride 128B)
//  F16A: 3 slots x 10240  (A fp16, row stride 80B)
//  F16B: 3 slots x 10240  (B fp16, row stride 80B)
//  [1024,..)  reused as Os[128][130] floats in the epilogue
#define F32A  1024
#define F16A  (F32A + 3 * 16384)
#define F16B  (F16A + 3 * 10240)
#define SMEM_BYTES (F16B + 3 * 10240)   // 111616

extern "C" __global__ void __launch_bounds__(256, 2)
fused1(const float* __restrict__ v, const int* __restrict__ batch,
       const float* __restrict__ b1, int N)
{
    extern __shared__ __align__(128) char smem[];
    int*   sbid = (int*)smem;
    float* Os   = (float*)(smem + 1024);
    uint32_t sb = smem_u32(smem);

    int t = threadIdx.x, lid = t & 31, wid = t >> 5;
    int wm = wid & 3, wn = wid >> 2;          // warp tile: rows wm*32, cols wn*64
    long long r0 = (long long)blockIdx.x * 128;
    int valid = N - (int)r0; if (valid > 128) valid = 128;
    if (t < 128) sbid[t] = (t < valid) ? batch[r0 + t] : -1;

    // Accumulators, bias-initialized. d[mt][nt][0..3]
    float d[2][8][4];
    {
        int cb = wn * 64 + 2 * (lid & 3);
#pragma unroll
        for (int nt = 0; nt < 8; ++nt) {
            float bx = __ldg(b1 + cb + nt * 8);
            float by = __ldg(b1 + cb + nt * 8 + 1);
#pragma unroll
            for (int mt = 0; mt < 2; ++mt) {
                d[mt][nt][0] = bx; d[mt][nt][1] = by;
                d[mt][nt][2] = bx; d[mt][nt][3] = by;
            }
        }
    }

    const float* vb = v + r0 * 256;
    int r8 = lid & 7, grp = lid >> 3;

    // cp.async A fp32 chunk ch -> slot
    auto cpA = [&](int ch, int slot) {
        uint32_t base = sb + F32A + slot * 16384;
#pragma unroll
        for (int q = 0; q < 4; ++q) {
            int idx = q * 256 + t, row = idx >> 3, f4 = idx & 7;
            int gr = (row < valid) ? row : (valid - 1);
            cp16(base + row * 128 + f4 * 16, vb + (long long)gr * 256 + ch * 32 + f4 * 4);
        }
    };
    // cp.async B fp16 chunk ch -> slot
    auto cpB = [&](int ch, int slot) {
        uint32_t base = sb + F16B + slot * 10240;
#pragma unroll
        for (int q = 0; q < 2; ++q) {
            int idx = q * 256 + t;
            int nn = idx >> 2, kk4 = idx & 3;
            cp16(base + nn * 80 + kk4 * 16, g_W1h + nn * 256 + ch * 32 + kk4 * 8);
        }
    };
    // convert f32 slot (ch%3) -> f16A slot (ch%3); 8 contiguous floats/thread/step
    auto convert = [&](int ch) {
        char* src = smem + F32A + (ch % 3) * 16384;
        char* dst = smem + F16A + (ch % 3) * 10240;
#pragma unroll
        for (int q = 0; q < 2; ++q) {
            int idx = q * 256 + t;              // 0..511
            int row = idx >> 2, e = idx & 3;    // 128 rows x 4 groups of 8 floats
            const float4* s4 = (const float4*)(src + row * 128 + e * 32);
            float4 a = s4[0], b = s4[1];
            __half2 h0 = __floats2half2_rn(a.x, a.y);
            __half2 h1 = __floats2half2_rn(a.z, a.w);
            __half2 h2 = __floats2half2_rn(b.x, b.y);
            __half2 h3 = __floats2half2_rn(b.z, b.w);
            *(uint4*)(dst + row * 80 + e * 16) = make_uint4(
                *(uint32_t*)&h0, *(uint32_t*)&h1, *(uint32_t*)&h2, *(uint32_t*)&h3);
        }
    };

    // ---- prologue ----
    cpA(0, 0); cpA(1, 1); cpB(0, 0); cpB(1, 1); CP_COMMIT();   // G1
    cpA(2, 2); CP_COMMIT();                                     // G2
    CP_WAIT1();            // G1 arrived
    __syncthreads();
    convert(0);            // f16A[0] ready
    __syncthreads();

    for (int c = 0; c < 8; ++c) {
        if (c < 7) convert(c + 1);                 // f32[(c+1)%3] -> f16A[(c+1)%3]
        if (c < 5) cpA(c + 3, (c + 3) % 3);
        if (c < 6) cpB(c + 2, (c + 2) % 3);
        CP_COMMIT();

        uint32_t abA = sb + F16A + (c % 3) * 10240;
        uint32_t abB = sb + F16B + (c % 3) * 10240;
#pragma unroll
        for (int kk = 0; kk < 2; ++kk) {
            int k0 = kk * 16;
            int arow = wm * 32 + r8 + (grp & 1) * 8;
            int acol = k0 + (grp >> 1) * 8;
            uint32_t afh[2][4];
#pragma unroll
            for (int mt = 0; mt < 2; ++mt)
                ldsm4(afh[mt], abA + (arow + mt * 16) * 80 + acol * 2);
#pragma unroll
            for (int ng = 0; ng < 4; ++ng) {
                int nrow = wn * 64 + ng * 16 + r8 + (grp >> 1) * 8;
                int ncol = k0 + (grp & 1) * 8;
                uint32_t bh[4];
                ldsm4(bh, abB + nrow * 80 + ncol * 2);
#pragma unroll
                for (int mt = 0; mt < 2; ++mt) {
#pragma unroll
                    for (int sub = 0; sub < 2; ++sub)
                        mma16816(d[mt][ng * 2 + sub], afh[mt], bh + 2 * sub);
                }
            }
        }

        CP_WAIT1();        // everything up to group G_{c-1} arrived
        __syncthreads();
    }

    // Epilogue: LeakyReLU, stage tile (stride 130 floats)
#pragma unroll
    for (int mt = 0; mt < 2; ++mt) {
        int rA = wm * 32 + mt * 16 + (lid >> 2);
#pragma unroll
        for (int nt = 0; nt < 8; ++nt) {
            int cc = wn * 64 + nt * 8 + 2 * (lid & 3);
            float x0 = d[mt][nt][0], x1 = d[mt][nt][1];
            float x2 = d[mt][nt][2], x3 = d[mt][nt][3];
            x0 = (x0 >= 0.f) ? x0 : NEG_SLOPE * x0;
            x1 = (x1 >= 0.f) ? x1 : NEG_SLOPE * x1;
            x2 = (x2 >= 0.f) ? x2 : NEG_SLOPE * x2;
            x3 = (x3 >= 0.f) ? x3 : NEG_SLOPE * x3;
            *(float2*)(Os + rA * 130 + cc)       = make_float2(x0, x1);
            *(float2*)(Os + (rA + 8) * 130 + cc) = make_float2(x2, x3);
        }
    }
    __syncthreads();

    // Segmented column-sum + counts (batch sorted -> few runs per tile)
    {
        int col = t & 127, half = t >> 7;
        int rb = half * 64;
        int re = rb + 64; if (re > valid) re = valid;
        if (rb < re) {
            int cur = sbid[rb];
            float acc = 0.f; int cnt = 0;
            for (int r = rb; r < re; ++r) {
                int g = sbid[r];
                if (g != cur) {
                    atomicAdd(&g_hsum[(long long)cur * HH + col], acc);
                    if (col == 0) atomicAdd(&g_counts[cur], (float)cnt);
                    acc = 0.f; cnt = 0; cur = g;
                }
                acc += Os[r * 130 + col];
                cnt++;
            }
            atomicAdd(&g_hsum[(long long)cur * HH + col], acc);
            if (col == 0) atomicAdd(&g_counts[cur], (float)cnt);
        }
    }
}

// out[g,:] = (hsum[g,:]/max(cnt,1)) @ W2 + b2 ; empty graphs -> 0. 16 graphs/block.
__global__ void __launch_bounds__(256)
kernelB(const float* __restrict__ W2, const float* __restrict__ b2,
        float* __restrict__ out, int G)
{
    __shared__ float sh[16][130];   // col 128 = non-empty flag
    int g0 = blockIdx.x * 16;
    int t = threadIdx.x;
    for (int idx = t; idx < 16 * 128; idx += 256) {
        int r = idx >> 7, k = idx & 127;
        int g = g0 + r;
        float val = 0.f, flag = 0.f;
        if (g < G) {
            float cnt = g_counts[g];
            float dn = (cnt < 1.f) ? 1.f : cnt;
            val = g_hsum[(long long)g * HH + k] / dn;
            flag = (cnt >= 0.5f) ? 1.f : 0.f;
        }
        sh[r][k] = val;
        if (k == 0) sh[r][128] = flag;
    }
    __syncthreads();

    int col = t & 127, rg = t >> 7;
    float bv = b2[col];
    float acc[8];
#pragma unroll
    for (int r = 0; r < 8; ++r) acc[r] = bv;
#pragma unroll 4
    for (int k = 0; k < 128; ++k) {
        float w = W2[k * O_DIM + col];
#pragma unroll
        for (int r = 0; r < 8; ++r) acc[r] += sh[rg * 8 + r][k] * w;
    }
#pragma unroll
    for (int r = 0; r < 8; ++r) {
        int g = g0 + rg * 8 + r;
        if (g < G) out[(long long)g * O_DIM + col] = acc[r] * sh[rg * 8 + r][128];
    }
}

extern "C" void kernel_launch(void* const* d_in, const int* in_sizes, int n_in,
                              void* d_out, int out_size)
{
    const float* v     = (const float*)d_in[0];
    const int*   batch = (const int*)d_in[1];
    int w = 2;
    if (n_in >= 7 && in_sizes[2] == 1) w = 3;   // skip num_graphs scalar if present
    const float* W1 = (const float*)d_in[w];
    const float* b1 = (const float*)d_in[w + 1];
    const float* W2 = (const float*)d_in[w + 2];
    const float* b2 = (const float*)d_in[w + 3];

    int N = in_sizes[1];
    int G = out_size / O_DIM;
    int hsumN = G * HH;

    int zn = hsumN; if (zn < G) zn = G; if (zn < 256 * 128) zn = 256 * 128;
    prep_kernel<<<(zn + 255) / 256, 256>>>(W1, hsumN, G);

    static int smem_set = 0;
    if (!smem_set) {
        cudaFuncSetAttribute((const void*)fused1,
                             cudaFuncAttributeMaxDynamicSharedMemorySize, SMEM_BYTES);
        smem_set = 1;
    }
    int nb = (N + 127) / 128;
    fused1<<<nb, 256, SMEM_BYTES>>>(v, batch, b1, N);

    kernelB<<<(G + 15) / 16, 256>>>(W2, b2, (float*)d_out, G);
}

// round 13
// speedup vs baseline: 1.4344x; 1.1930x over previous
#include <cuda_runtime.h>
#include <cuda_fp16.h>
#include <cstdint>

#define NEG_SLOPE 0.015f
#define HH    128
#define O_DIM 128

// Scratch: segment sums [G, HH], per-graph counts, fp16 transposed W1.
__device__ float g_hsum[1 << 21];
__device__ float g_counts[1 << 16];
__device__ __half g_W1h[128 * 256];   // [n][k], k contiguous

static __device__ __forceinline__ uint32_t smem_u32(const void* p) {
    uint32_t a;
    asm("{ .reg .u64 t; cvta.to.shared.u64 t, %1; cvt.u32.u64 %0, t; }" : "=r"(a) : "l"(p));
    return a;
}
static __device__ __forceinline__ void ldsm4(uint32_t* r, uint32_t addr) {
    asm volatile("ldmatrix.sync.aligned.m8n8.x4.shared.b16 {%0,%1,%2,%3}, [%4];"
                 : "=r"(r[0]), "=r"(r[1]), "=r"(r[2]), "=r"(r[3]) : "r"(addr));
}
static __device__ __forceinline__ void mma16816(float* d, const uint32_t* a,
                                                const uint32_t* b) {
    asm volatile("mma.sync.aligned.m16n8k16.row.col.f32.f16.f16.f32 "
                 "{%0,%1,%2,%3}, {%4,%5,%6,%7}, {%8,%9}, {%0,%1,%2,%3};"
                 : "+f"(d[0]), "+f"(d[1]), "+f"(d[2]), "+f"(d[3])
                 : "r"(a[0]), "r"(a[1]), "r"(a[2]), "r"(a[3]), "r"(b[0]), "r"(b[1]));
}
static __device__ __forceinline__ void cp16(uint32_t dst, const void* src) {
    asm volatile("cp.async.cg.shared.global [%0], [%1], 16;" :: "r"(dst), "l"(src));
}
#define CP_COMMIT() asm volatile("cp.async.commit_group;" ::: "memory")
#define CP_WAIT1()  asm volatile("cp.async.wait_group 1;" ::: "memory")

// Zero scratch + W1 -> fp16, transposed to [n][k].
__global__ void prep_kernel(const float* __restrict__ W1, int hsumN, int G) {
    int i = blockIdx.x * blockDim.x + threadIdx.x;
    if (i < hsumN) g_hsum[i] = 0.f;
    if (i < G)     g_counts[i] = 0.f;
    if (i < 256 * 128) {
        int k = i >> 7, n = i & 127;          // W1 is [256][128] row-major
        g_W1h[n * 256 + k] = __float2half_rn(W1[i]);
    }
}

// No-op spacers: shift fused1 to captured-launch ordinal #4 for ncu.
__global__ void dummy_kernel() {}

// SMEM (bytes):
//  [0,512)     sbid[128]
//  F32A: 3 slots x 16384  (A fp32 staging, row stride 128B)
//  F16A: 2 slots x 10240  (A fp16, row stride 80B)
//  F16B: 3 slots x 10240  (B fp16, row stride 80B)
//  [1024,..)  reused as OsH[128][136] __half in the epilogue (34816B)
#define F32A  1024
#define F16A  (F32A + 3 * 16384)
#define F16B  (F16A + 2 * 10240)
#define SMEM_BYTES (F16B + 3 * 10240)   // 101376

extern "C" __global__ void __launch_bounds__(256, 2)
fused1(const float* __restrict__ v, const int* __restrict__ batch,
       const float* __restrict__ b1, int N)
{
    extern __shared__ __align__(128) char smem[];
    int*    sbid = (int*)smem;
    __half* OsH  = (__half*)(smem + 1024);
    uint32_t sb = smem_u32(smem);

    int t = threadIdx.x, lid = t & 31, wid = t >> 5;
    int wm = wid & 3, wn = wid >> 2;          // warp tile: rows wm*32, cols wn*64
    long long r0 = (long long)blockIdx.x * 128;
    int valid = N - (int)r0; if (valid > 128) valid = 128;
    if (t < 128) sbid[t] = (t < valid) ? batch[r0 + t] : -1;

    // Accumulators, bias-initialized. d[mt][nt][0..3]
    float d[2][8][4];
    {
        int cb = wn * 64 + 2 * (lid & 3);
#pragma unroll
        for (int nt = 0; nt < 8; ++nt) {
            float bx = __ldg(b1 + cb + nt * 8);
            float by = __ldg(b1 + cb + nt * 8 + 1);
#pragma unroll
            for (int mt = 0; mt < 2; ++mt) {
                d[mt][nt][0] = bx; d[mt][nt][1] = by;
                d[mt][nt][2] = bx; d[mt][nt][3] = by;
            }
        }
    }

    const float* vb = v + r0 * 256;
    int r8 = lid & 7, grp = lid >> 3;

    // cp.async A fp32 chunk ch -> slot
    auto cpA = [&](int ch, int slot) {
        uint32_t base = sb + F32A + slot * 16384;
#pragma unroll
        for (int q = 0; q < 4; ++q) {
            int idx = q * 256 + t, row = idx >> 3, f4 = idx & 7;
            int gr = (row < valid) ? row : (valid - 1);
            cp16(base + row * 128 + f4 * 16, vb + (long long)gr * 256 + ch * 32 + f4 * 4);
        }
    };
    // cp.async B fp16 chunk ch -> slot
    auto cpB = [&](int ch, int slot) {
        uint32_t base = sb + F16B + slot * 10240;
#pragma unroll
        for (int q = 0; q < 2; ++q) {
            int idx = q * 256 + t;
            int nn = idx >> 2, kk4 = idx & 3;
            cp16(base + nn * 80 + kk4 * 16, g_W1h + nn * 256 + ch * 32 + kk4 * 8);
        }
    };
    // convert f32 slot (ch%3) -> f16A slot (ch&1)   [R9 conflict-free mapping]
    auto convert = [&](int ch) {
        char* src = smem + F32A + (ch % 3) * 16384;
        char* dst = smem + F16A + (ch & 1) * 10240;
#pragma unroll
        for (int q = 0; q < 4; ++q) {
            int idx = q * 256 + t, row = idx >> 3, f4 = idx & 7;
            float4 a = *(const float4*)(src + row * 128 + f4 * 16);
            __half2 h01 = __floats2half2_rn(a.x, a.y);
            __half2 h23 = __floats2half2_rn(a.z, a.w);
            *(uint2*)(dst + row * 80 + f4 * 8) =
                make_uint2(*(uint32_t*)&h01, *(uint32_t*)&h23);
        }
    };

    // ---- prologue ----
    cpA(0, 0); cpA(1, 1); cpB(0, 0); cpB(1, 1); CP_COMMIT();   // G1
    cpA(2, 2); CP_COMMIT();                                     // G2
    CP_WAIT1();            // G1 arrived
    __syncthreads();
    convert(0);            // f16A[0] ready
    __syncthreads();

    for (int c = 0; c < 8; ++c) {
        int s = c & 1;
        if (c < 7) convert(c + 1);                 // f32[(c+1)%3] -> f16A[s^1]
        if (c < 5) cpA(c + 3, (c + 3) % 3);
        if (c < 6) cpB(c + 2, (c + 2) % 3);
        CP_COMMIT();

        uint32_t abA = sb + F16A + s * 10240;
        uint32_t abB = sb + F16B + (c % 3) * 10240;
#pragma unroll
        for (int kk = 0; kk < 2; ++kk) {
            int k0 = kk * 16;
            int arow = wm * 32 + r8 + (grp & 1) * 8;
            int acol = k0 + (grp >> 1) * 8;
            uint32_t afh[2][4];
#pragma unroll
            for (int mt = 0; mt < 2; ++mt)
                ldsm4(afh[mt], abA + (arow + mt * 16) * 80 + acol * 2);
#pragma unroll
            for (int ng = 0; ng < 4; ++ng) {
                int nrow = wn * 64 + ng * 16 + r8 + (grp >> 1) * 8;
                int ncol = k0 + (grp & 1) * 8;
                uint32_t bh[4];
                ldsm4(bh, abB + nrow * 80 + ncol * 2);
#pragma unroll
                for (int mt = 0; mt < 2; ++mt) {
#pragma unroll
                    for (int sub = 0; sub < 2; ++sub)
                        mma16816(d[mt][ng * 2 + sub], afh[mt], bh + 2 * sub);
                }
            }
        }

        CP_WAIT1();        // everything up to group G_{c-1} arrived
        __syncthreads();
    }

    // Epilogue: LeakyReLU, stage tile as fp16 (stride 136 halves = 272B,
    // 68-bank rotation -> conflict-free half2 stores)
#pragma unroll
    for (int mt = 0; mt < 2; ++mt) {
        int rA = wm * 32 + mt * 16 + (lid >> 2);
#pragma unroll
        for (int nt = 0; nt < 8; ++nt) {
            int cc = wn * 64 + nt * 8 + 2 * (lid & 3);
            float x0 = d[mt][nt][0], x1 = d[mt][nt][1];
            float x2 = d[mt][nt][2], x3 = d[mt][nt][3];
            x0 = (x0 >= 0.f) ? x0 : NEG_SLOPE * x0;
            x1 = (x1 >= 0.f) ? x1 : NEG_SLOPE * x1;
            x2 = (x2 >= 0.f) ? x2 : NEG_SLOPE * x2;
            x3 = (x3 >= 0.f) ? x3 : NEG_SLOPE * x3;
            *(__half2*)(OsH + rA * 136 + cc)       = __floats2half2_rn(x0, x1);
            *(__half2*)(OsH + (rA + 8) * 136 + cc) = __floats2half2_rn(x2, x3);
        }
    }
    __syncthreads();

    // Segmented column-sum + counts (batch sorted -> few runs per tile)
    {
        int col = t & 127, half = t >> 7;
        int rb = half * 64;
        int re = rb + 64; if (re > valid) re = valid;
        if (rb < re) {
            int cur = sbid[rb];
            float acc = 0.f; int cnt = 0;
            for (int r = rb; r < re; ++r) {
                int g = sbid[r];
                if (g != cur) {
                    atomicAdd(&g_hsum[(long long)cur * HH + col], acc);
                    if (col == 0) atomicAdd(&g_counts[cur], (float)cnt);
                    acc = 0.f; cnt = 0; cur = g;
                }
                acc += __half2float(OsH[r * 136 + col]);
                cnt++;
            }
            atomicAdd(&g_hsum[(long long)cur * HH + col], acc);
            if (col == 0) atomicAdd(&g_counts[cur], (float)cnt);
        }
    }
}

// out[g,:] = (hsum[g,:]/max(cnt,1)) @ W2 + b2 ; empty graphs -> 0. 16 graphs/block.
__global__ void __launch_bounds__(256)
kernelB(const float* __restrict__ W2, const float* __restrict__ b2,
        float* __restrict__ out, int G)
{
    __shared__ float sh[16][130];   // col 128 = non-empty flag
    int g0 = blockIdx.x * 16;
    int t = threadIdx.x;
    for (int idx = t; idx < 16 * 128; idx += 256) {
        int r = idx >> 7, k = idx & 127;
        int g = g0 + r;
        float val = 0.f, flag = 0.f;
        if (g < G) {
            float cnt = g_counts[g];
            float dn = (cnt < 1.f) ? 1.f : cnt;
            val = g_hsum[(long long)g * HH + k] / dn;
            flag = (cnt >= 0.5f) ? 1.f : 0.f;
        }
        sh[r][k] = val;
        if (k == 0) sh[r][128] = flag;
    }
    __syncthreads();

    int col = t & 127, rg = t >> 7;
    float bv = b2[col];
    float acc[8];
#pragma unroll
    for (int r = 0; r < 8; ++r) acc[r] = bv;
#pragma unroll 4
    for (int k = 0; k < 128; ++k) {
        float w = W2[k * O_DIM + col];
#pragma unroll
        for (int r = 0; r < 8; ++r) acc[r] += sh[rg * 8 + r][k] * w;
    }
#pragma unroll
    for (int r = 0; r < 8; ++r) {
        int g = g0 + rg * 8 + r;
        if (g < G) out[(long long)g * O_DIM + col] = acc[r] * sh[rg * 8 + r][128];
    }
}

extern "C" void kernel_launch(void* const* d_in, const int* in_sizes, int n_in,
                              void* d_out, int out_size)
{
    const float* v     = (const float*)d_in[0];
    const int*   batch = (const int*)d_in[1];
    int w = 2;
    if (n_in >= 7 && in_sizes[2] == 1) w = 3;   // skip num_graphs scalar if present
    const float* W1 = (const float*)d_in[w];
    const float* b1 = (const float*)d_in[w + 1];
    const float* W2 = (const float*)d_in[w + 2];
    const float* b2 = (const float*)d_in[w + 3];

    int N = in_sizes[1];
    int G = out_size / O_DIM;
    int hsumN = G * HH;

    int zn = hsumN; if (zn < G) zn = G; if (zn < 256 * 128) zn = 256 * 128;
    prep_kernel<<<(zn + 255) / 256, 256>>>(W1, hsumN, G);

    // Spacers so fused1 is captured-launch #4 for ncu.
    dummy_kernel<<<1, 32>>>();
    dummy_kernel<<<1, 32>>>();

    static int smem_set = 0;
    if (!smem_set) {
        cudaFuncSetAttribute((const void*)fused1,
                             cudaFuncAttributeMaxDynamicSharedMemorySize, SMEM_BYTES);
        smem_set = 1;
    }
    int nb = (N + 127) / 128;
    fused1<<<nb, 256, SMEM_BYTES>>>(v, batch, b1, N);

    kernelB<<<(G + 15) / 16, 256>>>(W2, b2, (float*)d_out, G);
}